// round 12
// baseline (speedup 1.0000x reference)
#include <cuda_runtime.h>
#include <cuda_fp16.h>
#include <math.h>
#include <stdint.h>

#define BATCH 256
#define NCLS  10
#define CC    128
#define OCH   256

// GEMM tiling: KC=32, pure fp16 single pass (Ah, Bh)
#define TSTRIDE 40                // fp16 elems per smem row (80B)
#define TILEB   (128*TSTRIDE*2)   // 10240 B per 128x32 fp16 tile
#define STAGEB  (2*TILEB)         // Ah,Bh = 20480 B
#define GSMEM0  (2*STAGEB)        // double buffered = 40960 B (+ ktab)

// ---------------- static device scratch, per-branch offsets ----------------
__device__ float g_x2[BATCH*14*14];
__device__ float g_x1[BATCH*7*7];
__device__ float g_y [17203200];
__device__ float g_mean[3*CC];
__device__ float g_rstd[3*CC];
__device__ float g_bnp[3*CC*8*2];
__device__ float g_badj[3*OCH];
__device__ int   g_ktab[14720];
__device__ __half g_wh[3768320];
__device__ float g_dwt[2007040];            // transposed routing weights [n][r][o][i]
__device__ float g_p [3211264];
__device__ float g_u [3211264];
__device__ float g_len[3*BATCH*NCLS];

// ---------------- PTX helpers ----------------
__device__ __forceinline__ uint32_t smem_u32(const void* p) {
    uint32_t a;
    asm("{ .reg .u64 t; cvta.to.shared.u64 t, %1; cvt.u32.u64 %0, t; }" : "=r"(a) : "l"(p));
    return a;
}
#define CP_ASYNC16(dst, src) \
    asm volatile("cp.async.ca.shared.global [%0], [%1], 16;" :: "r"(dst), "l"(src) : "memory")
#define CP_COMMIT() asm volatile("cp.async.commit_group;" ::: "memory")
#define CP_WAIT0()  asm volatile("cp.async.wait_group 0;" ::: "memory")

__device__ __forceinline__ void ldmx4(uint32_t addr, uint32_t& r0, uint32_t& r1,
                                      uint32_t& r2, uint32_t& r3) {
    asm volatile("ldmatrix.sync.aligned.m8n8.x4.shared.b16 {%0,%1,%2,%3}, [%4];"
                 : "=r"(r0), "=r"(r1), "=r"(r2), "=r"(r3) : "r"(addr));
}
__device__ __forceinline__ void mma16816(float* c, const uint32_t* a, uint32_t b0, uint32_t b1) {
    asm volatile(
        "mma.sync.aligned.m16n8k16.row.col.f32.f16.f16.f32 "
        "{%0,%1,%2,%3}, {%4,%5,%6,%7}, {%8,%9}, {%0,%1,%2,%3};"
        : "+f"(c[0]), "+f"(c[1]), "+f"(c[2]), "+f"(c[3])
        : "r"(a[0]), "r"(a[1]), "r"(a[2]), "r"(a[3]), "r"(b0), "r"(b1));
}

// ---------------- pooling ----------------
__global__ void pool2_kernel(const float* __restrict__ img) {
    int idx = blockIdx.x*blockDim.x + threadIdx.x;
    if (idx >= BATCH*14*14) return;
    int j = idx % 14, i = (idx/14) % 14, b = idx/196;
    const float* p = img + b*784;
    g_x2[idx] = 0.25f*(p[(2*i)*28+2*j] + p[(2*i)*28+2*j+1]
                     + p[(2*i+1)*28+2*j] + p[(2*i+1)*28+2*j+1]);
}
__global__ void pool1_kernel() {
    int idx = blockIdx.x*blockDim.x + threadIdx.x;
    if (idx >= BATCH*7*7) return;
    int j = idx % 7, i = (idx/7) % 7, b = idx/49;
    const float* p = g_x2 + b*196;
    g_x1[idx] = 0.25f*(p[(2*i)*14+2*j] + p[(2*i)*14+2*j+1]
                     + p[(2*i+1)*14+2*j] + p[(2*i+1)*14+2*j+1]);
}

// ---------------- conv stage A: 8 groups x 16 channels per image ----------------
template<int K1, int H, int H1>
__global__ __launch_bounds__(256) void convA_smem(const float* __restrict__ xin_ext, int src,
                                                  const float* __restrict__ w,
                                                  const float* __restrict__ bias,
                                                  size_t yo)
{
    __shared__ float s_in[H*H];
    __shared__ float s_w[16*K1*K1];
    int b = blockIdx.x;
    int c0 = blockIdx.y * 16;
    int tid = threadIdx.x;
    const float* xin = (src == 0) ? xin_ext : (src == 1 ? g_x2 : g_x1);
    const float* ip = xin + b*H*H;
    for (int i = tid; i < H*H; i += 256) s_in[i] = ip[i];
    for (int i = tid; i < 16*K1*K1; i += 256) s_w[i] = w[c0*K1*K1 + i];
    __syncthreads();

    for (int pair = tid; pair < 16*H1; pair += 256) {
        int cl = pair & 15, oy = pair >> 4;
        int c = c0 + cl;
        float bv = __ldg(&bias[c]);
        float acc[H1];
#pragma unroll
        for (int ox = 0; ox < H1; ox++) acc[ox] = bv;
        const float* wc = s_w + cl*K1*K1;
#pragma unroll
        for (int ky = 0; ky < K1; ky++) {
            float row[H1 + K1 - 1];
            const float* rp = s_in + (oy + ky)*H;
#pragma unroll
            for (int x = 0; x < H1 + K1 - 1; x++) row[x] = rp[x];
#pragma unroll
            for (int kx = 0; kx < K1; kx++) {
                float wv = wc[ky*K1 + kx];
#pragma unroll
                for (int ox = 0; ox < H1; ox++)
                    acc[ox] = fmaf(wv, row[ox + kx], acc[ox]);
            }
        }
        float* op = g_y + yo + ((size_t)(b*CC + c)*H1 + oy)*H1;
#pragma unroll
        for (int ox = 0; ox < H1; ox++) op[ox] = fmaxf(acc[ox], 0.f);
    }
}

// ---------------- batchnorm stats: two-phase ----------------
__global__ void bn_partial_kernel(int HW, size_t yo, int br) {
    int c = blockIdx.x, sl = blockIdx.y;
    int tid = threadIdx.x;
    const float* yb = g_y + yo;
    float s = 0.f, s2 = 0.f;
    int total = 32*HW;
    for (int i = tid; i < total; i += 256) {
        int b = sl*32 + i/HW;
        int hw = i - (i/HW)*HW;
        float v = yb[(size_t)(b*CC + c)*HW + hw];
        s += v; s2 += v*v;
    }
#pragma unroll
    for (int off = 16; off; off >>= 1) {
        s  += __shfl_xor_sync(0xffffffffu, s,  off);
        s2 += __shfl_xor_sync(0xffffffffu, s2, off);
    }
    __shared__ float rs[8], rq[8];
    if ((tid & 31) == 0) { rs[tid>>5] = s; rq[tid>>5] = s2; }
    __syncthreads();
    if (tid == 0) {
        float a = 0.f, b2 = 0.f;
#pragma unroll
        for (int w = 0; w < 8; w++) { a += rs[w]; b2 += rq[w]; }
        g_bnp[((br*CC + c)*8 + sl)*2 + 0] = a;
        g_bnp[((br*CC + c)*8 + sl)*2 + 1] = b2;
    }
}
__global__ void bn_final_kernel(int HW, int br) {
    int c = threadIdx.x;
    float s = 0.f, s2 = 0.f;
#pragma unroll
    for (int sl = 0; sl < 8; sl++) {
        s  += g_bnp[((br*CC + c)*8 + sl)*2 + 0];
        s2 += g_bnp[((br*CC + c)*8 + sl)*2 + 1];
    }
    float N = (float)(BATCH*HW);
    float m = s / N;
    float var = s2 / N - m*m;
    g_mean[br*CC + c] = m;
    g_rstd[br*CC + c] = rsqrtf(var + 1e-5f);
}

// ---------------- prep ----------------
__global__ void prep_ktab_kernel(int K, int kp, int H1, size_t ko) {
    int kidx = blockIdx.x*blockDim.x + threadIdx.x;
    if (kidx >= K) return;
    int kk2 = kp*kp;
    int ic = kidx / kk2;
    int rem = kidx - ic*kk2;
    int off = ic*H1*H1 + (rem/kp)*H1 + (rem % kp);
    g_ktab[ko + kidx] = (ic << 20) | off;
}
__global__ void prep_w_kernel(const float* __restrict__ pw, int K, size_t wo,
                              size_t ko, int br) {
    int idx = blockIdx.x*blockDim.x + threadIdx.x;
    if (idx >= OCH*K) return;
    int k = idx - (idx/K)*K;
    int c = g_ktab[ko + k] >> 20;
    float v = pw[idx] * g_rstd[br*CC + c];
    g_wh[wo + idx] = __float2half_rn(v);
}
__global__ void prep_badj_kernel(const float* __restrict__ pw,
                                 const float* __restrict__ pb,
                                 int K, size_t ko, int br) {
    int oc = blockIdx.x;
    int tid = threadIdx.x;
    float s = 0.f;
    for (int k = tid; k < K; k += 256) {
        int c = g_ktab[ko + k] >> 20;
        s += pw[(size_t)oc*K + k] * g_mean[br*CC + c] * g_rstd[br*CC + c];
    }
#pragma unroll
    for (int off = 16; off; off >>= 1) s += __shfl_xor_sync(0xffffffffu, s, off);
    __shared__ float rs[8];
    if ((tid & 31) == 0) rs[tid>>5] = s;
    __syncthreads();
    if (tid == 0) {
        float a = 0.f;
#pragma unroll
        for (int w = 0; w < 8; w++) a += rs[w];
        g_badj[br*OCH + oc] = pb[oc] - a;
    }
}
// transpose routing weights: dwt[n][r][o][i] = dw[n][r][i][o]
__global__ void prep_dwt_kernel(const float* __restrict__ dw, int R, size_t dwto) {
    int idx = blockIdx.x*blockDim.x + threadIdx.x;
    if (idx >= NCLS*R*128) return;
    int i = idx & 7;
    int o = (idx >> 3) & 15;
    int nr = idx >> 7;
    g_dwt[dwto + idx] = dw[(size_t)nr*128 + i*16 + o];
}

// ---------------- prim conv GEMM: inline im2col + pure fp16 mma ----------------
__device__ __forceinline__ void load_B(uint32_t sb, int buf, int n0, int kc, int K,
                                       size_t wo, int tid)
{
    uint32_t dst0 = sb + buf*STAGEB + TILEB;
#pragma unroll
    for (int i = 0; i < 2; i++) {
        int q = tid + i*256;
        int row = q >> 2, ch = q & 3;
        const __half* src = g_wh + wo + (size_t)(n0+row)*K + kc + ch*8;
        CP_ASYNC16(dst0 + row*(TSTRIDE*2) + ch*16, src);
    }
}
__device__ __forceinline__ void gather_A(const float* __restrict__ yb,
                                         const int* rowbase, const int* s_kt,
                                         int kc, int lane, float* f)
{
    int off = s_kt[kc + lane];
#pragma unroll
    for (int j = 0; j < 16; j++) f[j] = yb[rowbase[j] + off];
}
__device__ __forceinline__ void convert_sts_A(char* smem, int buf,
                                              int wid, int lane, const float* f)
{
    char* base = smem + buf*STAGEB + (wid*16)*(TSTRIDE*2) + lane*2;
#pragma unroll
    for (int j = 0; j < 16; j++) {
        *(__half*)(base + j*(TSTRIDE*2)) = __float2half_rn(f[j]);
    }
}

__global__ __launch_bounds__(256) void prim_mma_kernel(int S, int Hp, int H1, int K,
                                                       size_t yo, size_t ko,
                                                       size_t wo, size_t po, int br)
{
    extern __shared__ char smem[];
    int* s_kt = (int*)(smem + GSMEM0);
    uint32_t sb = smem_u32(smem);
    int tid = threadIdx.x, wid = tid >> 5, lane = tid & 31;
    int n0 = (blockIdx.x & 1) << 7;
    int m0 = (int)(blockIdx.x >> 1) << 7;

    for (int k = tid; k < K; k += 256) s_kt[k] = g_ktab[ko + k] & 0xFFFFF;

    int rowbase[16];
#pragma unroll
    for (int j = 0; j < 16; j++) {
        int m = m0 + wid*16 + j;
        int b = m / S, s = m - b*S;
        int oy = s / Hp, ox = s - oy*Hp;
        rowbase[j] = b*CC*H1*H1 + (oy*2)*H1 + ox*2;
    }
    __syncthreads();

    const float* yb = g_y + yo;

    int wm = (wid & 3) << 5;
    int wn = (wid >> 2) << 6;

    float acc[2][8][4];
#pragma unroll
    for (int mt = 0; mt < 2; mt++)
#pragma unroll
        for (int nb = 0; nb < 8; nb++)
#pragma unroll
            for (int j = 0; j < 4; j++) acc[mt][nb][j] = 0.f;

    int nch = K >> 5;

    load_B(sb, 0, n0, 0, K, wo, tid);
    CP_COMMIT();
    {
        float f[16];
        gather_A(yb, rowbase, s_kt, 0, lane, f);
        convert_sts_A(smem, 0, wid, lane, f);
    }
    CP_WAIT0();
    __syncthreads();

    uint32_t aLaneOff = (uint32_t)((lane & 15)*(TSTRIDE*2) + (lane >> 4)*16);
    uint32_t bLaneOff = (uint32_t)((((lane >> 3) & 3)*8 + (lane & 7))*(TSTRIDE*2));

    for (int c = 0; c < nch; c++) {
        int p = c & 1, q = p ^ 1;
        float f[16];
        if (c + 1 < nch) {
            load_B(sb, q, n0, (c + 1) << 5, K, wo, tid);
            CP_COMMIT();
            gather_A(yb, rowbase, s_kt, (c + 1) << 5, lane, f);
        }

        uint32_t st = sb + p*STAGEB;
#pragma unroll
        for (int kk = 0; kk < 2; kk++) {
            uint32_t ah[2][4];
#pragma unroll
            for (int mt = 0; mt < 2; mt++)
                ldmx4(st + (wm + mt*16)*(TSTRIDE*2) + kk*32 + aLaneOff,
                      ah[mt][0], ah[mt][1], ah[mt][2], ah[mt][3]);
            uint32_t bh[8][2];
#pragma unroll
            for (int g = 0; g < 2; g++)
#pragma unroll
                for (int kh = 0; kh < 2; kh++) {
                    uint32_t r0, r1, r2, r3;
                    ldmx4(st + TILEB + (wn + g*32)*(TSTRIDE*2) + kk*32 + kh*16 + bLaneOff,
                          r0, r1, r2, r3);
                    bh[g*4+0][kh] = r0; bh[g*4+1][kh] = r1;
                    bh[g*4+2][kh] = r2; bh[g*4+3][kh] = r3;
                }
#pragma unroll
            for (int mt = 0; mt < 2; mt++)
#pragma unroll
                for (int nb = 0; nb < 8; nb++)
                    mma16816(acc[mt][nb], ah[mt], bh[nb][0], bh[nb][1]);
        }

        if (c + 1 < nch) {
            convert_sts_A(smem, q, wid, lane, f);
            CP_WAIT0();
        }
        __syncthreads();
    }

    int gr = lane >> 2, tc = lane & 3;
    float* gp = g_p + po;
    const float* badj = g_badj + br*OCH;
#pragma unroll
    for (int mt = 0; mt < 2; mt++) {
        int mA = m0 + wm + mt*16 + gr;
        int mB = mA + 8;
#pragma unroll
        for (int nb = 0; nb < 8; nb++) {
            int oc = n0 + wn + nb*8 + tc*2;
            float bias0 = badj[oc], bias1 = badj[oc+1];
            float2 vA = make_float2(acc[mt][nb][0] + bias0, acc[mt][nb][1] + bias1);
            float2 vB = make_float2(acc[mt][nb][2] + bias0, acc[mt][nb][3] + bias1);
            *reinterpret_cast<float2*>(gp + (size_t)mA*OCH + oc) = vA;
            *reinterpret_cast<float2*>(gp + (size_t)mB*OCH + oc) = vB;
        }
    }
}

// ---------------- squash primary capsules (coalesced) ----------------
__global__ void squash_u_kernel(int S, int R, size_t po, size_t uo) {
    int idx = blockIdx.x*blockDim.x + threadIdx.x;
    if (idx >= BATCH*R) return;
    int c32 = idx & 31;
    int bs  = idx >> 5;
    int b = bs / S, s = bs - b*S;
    const float* pp = g_p + po + (size_t)bs*OCH + c32;
    float t[8]; float sn = 0.f;
#pragma unroll
    for (int i = 0; i < 8; i++) {
        t[i] = pp[i*32];
        sn += t[i]*t[i];
    }
    float scale = sn/(1.f + sn) * rsqrtf(sn + 1e-12f);
    int r = c32*S + s;
    float* up = g_u + uo + ((size_t)b*R + r)*8;
#pragma unroll
    for (int i = 0; i < 8; i++)
        up[i] = t[i]*scale;
}

// ---------------- fused priors + dynamic routing (1 batch per CTA) ----------------
__global__ void routing_fused_kernel(int R, int br, size_t uo, size_t dwto) {
    int b = blockIdx.x, n = blockIdx.y;
    extern __shared__ float sm[];
    float* P    = sm;
    float* blog = P + R*16;
    float* wred = blog + R;
    float* vv   = wred + 128;
    float* sred = vv + 16;
    float* scal = sred + 8;

    int tid = threadIdx.x;
    // P build: one thread per capsule-row r; u loaded once, dwt contiguous
    for (int r = tid; r < R; r += 256) {
        const float4* up4 = reinterpret_cast<const float4*>(g_u + uo + ((size_t)b*R + r)*8);
        float4 u0 = up4[0], u1 = up4[1];
        const float4* wt = reinterpret_cast<const float4*>(g_dwt + dwto + ((size_t)n*R + r)*128);
        float* Pr = P + r*16;
#pragma unroll
        for (int o = 0; o < 16; o++) {
            float4 wa = wt[o*2], wb = wt[o*2+1];
            float s = u0.x*wa.x + u0.y*wa.y + u0.z*wa.z + u0.w*wa.w
                    + u1.x*wb.x + u1.y*wb.y + u1.z*wb.z + u1.w*wb.w;
            Pr[o] = s;
        }
    }
    for (int r = tid; r < R; r += 256) blog[r] = 0.f;
    __syncthreads();

    for (int it = 0; it < 3; it++) {
        float mx = -1e30f;
        for (int r = tid; r < R; r += 256) mx = fmaxf(mx, blog[r]);
#pragma unroll
        for (int off = 16; off; off >>= 1)
            mx = fmaxf(mx, __shfl_xor_sync(0xffffffffu, mx, off));
        if ((tid & 31) == 0) sred[tid >> 5] = mx;
        __syncthreads();
        if (tid == 0) {
            float m = sred[0];
            for (int w2 = 1; w2 < 8; w2++) m = fmaxf(m, sred[w2]);
            scal[0] = m;
        }
        __syncthreads();
        float gmax = scal[0];
        float se = 0.f;
        for (int r = tid; r < R; r += 256) se += expf(blog[r] - gmax);
#pragma unroll
        for (int off = 16; off; off >>= 1)
            se += __shfl_xor_sync(0xffffffffu, se, off);
        if ((tid & 31) == 0) sred[tid >> 5] = se;
        __syncthreads();
        if (tid == 0) {
            float s = 0.f;
            for (int w2 = 0; w2 < 8; w2++) s += sred[w2];
            scal[1] = 1.f/s;
        }
        __syncthreads();
        float isum = scal[1];
        float acc[16];
#pragma unroll
        for (int o = 0; o < 16; o++) acc[o] = 0.f;
        for (int r = tid; r < R; r += 256) {
            float c = expf(blog[r] - gmax)*isum;
            const float* pr = P + r*16;
#pragma unroll
            for (int o = 0; o < 16; o++) acc[o] += c*pr[o];
        }
#pragma unroll
        for (int o = 0; o < 16; o++) {
            float v = acc[o];
#pragma unroll
            for (int off = 16; off; off >>= 1)
                v += __shfl_xor_sync(0xffffffffu, v, off);
            acc[o] = v;
        }
        if ((tid & 31) == 0)
#pragma unroll
            for (int o = 0; o < 16; o++) wred[(tid >> 5)*16 + o] = acc[o];
        __syncthreads();
        if (tid == 0) {
            float s16[16]; float sn = 0.f;
#pragma unroll
            for (int o = 0; o < 16; o++) {
                float s = 0.f;
                for (int w2 = 0; w2 < 8; w2++) s += wred[w2*16 + o];
                s16[o] = s; sn += s*s;
            }
            float sc = sn/(1.f + sn) * rsqrtf(sn + 1e-12f);
#pragma unroll
            for (int o = 0; o < 16; o++) vv[o] = s16[o]*sc;
        }
        __syncthreads();
        if (it < 2) {
            for (int r = tid; r < R; r += 256) {
                const float* pr = P + r*16;
                float d = 0.f;
#pragma unroll
                for (int o = 0; o < 16; o++) d += pr[o]*vv[o];
                blog[r] += d;
            }
            __syncthreads();
        }
    }
    if (tid == 0) {
        float s = 0.f;
#pragma unroll
        for (int o = 0; o < 16; o++) s += vv[o]*vv[o];
        g_len[br*BATCH*NCLS + b*NCLS + n] = sqrtf(s + 1e-12f);
    }
}

// ---------------- final ----------------
__global__ void final_kernel(float* __restrict__ out) {
    int b = blockIdx.x*blockDim.x + threadIdx.x;
    if (b >= BATCH) return;
    float l[NCLS]; float mx = -1e30f;
#pragma unroll
    for (int n = 0; n < NCLS; n++) {
        l[n] = g_len[0*BATCH*NCLS + b*NCLS + n]
             + g_len[1*BATCH*NCLS + b*NCLS + n]
             + g_len[2*BATCH*NCLS + b*NCLS + n];
        mx = fmaxf(mx, l[n]);
    }
    float s = 0.f;
#pragma unroll
    for (int n = 0; n < NCLS; n++) { l[n] = expf(l[n] - mx); s += l[n]; }
    float inv = 1.f/s;
#pragma unroll
    for (int n = 0; n < NCLS; n++) out[b*NCLS + n] = l[n]*inv;
}

// ---------------- host driver ----------------
struct BranchCfg {
    int src;
    int H, k1, H1, kp, Hp, S, R, K;
    int iw, br;
    size_t yo, ko, wo, po, uo, dwto;
};

static void run_branch(const BranchCfg& c, void* const* d_in, const float* x,
                       cudaStream_t st)
{
    const float* cw = (const float*)d_in[c.iw + 0];
    const float* cb = (const float*)d_in[c.iw + 1];
    const float* pw = (const float*)d_in[c.iw + 2];
    const float* pb = (const float*)d_in[c.iw + 3];
    const float* dw = (const float*)d_in[c.iw + 4];

    int HW = c.H1*c.H1;
    prep_ktab_kernel<<<(c.K + 255)/256, 256, 0, st>>>(c.K, c.kp, c.H1, c.ko);
    prep_dwt_kernel<<<(NCLS*c.R*128 + 255)/256, 256, 0, st>>>(dw, c.R, c.dwto);
    dim3 cgrid(BATCH, 8);
    if (c.k1 == 3)      convA_smem<3, 7, 5  ><<<cgrid, 256, 0, st>>>(x, c.src, cw, cb, c.yo);
    else if (c.k1 == 5) convA_smem<5, 14, 10><<<cgrid, 256, 0, st>>>(x, c.src, cw, cb, c.yo);
    else                convA_smem<9, 28, 20><<<cgrid, 256, 0, st>>>(x, c.src, cw, cb, c.yo);
    bn_partial_kernel<<<dim3(CC, 8), 256, 0, st>>>(HW, c.yo, c.br);
    bn_final_kernel<<<1, CC, 0, st>>>(HW, c.br);

    prep_w_kernel<<<(OCH*c.K + 255)/256, 256, 0, st>>>(pw, c.K, c.wo, c.ko, c.br);
    prep_badj_kernel<<<OCH, 256, 0, st>>>(pw, pb, c.K, c.ko, c.br);

    int M = BATCH*c.S;
    int gsmem = GSMEM0 + c.K*4;
    prim_mma_kernel<<<2*(M/128), 256, gsmem, st>>>(c.S, c.Hp, c.H1, c.K,
                                                   c.yo, c.ko, c.wo, c.po, c.br);

    squash_u_kernel<<<(BATCH*c.R + 255)/256, 256, 0, st>>>(c.S, c.R, c.po, c.uo);

    int smemR = (c.R*17 + 128 + 16 + 8 + 2)*(int)sizeof(float);
    dim3 rgrid(BATCH, NCLS);
    routing_fused_kernel<<<rgrid, 256, smemR, st>>>(c.R, c.br, c.uo, c.dwto);
}

extern "C" void kernel_launch(void* const* d_in, const int* in_sizes, int n_in,
                              void* d_out, int out_size)
{
    (void)in_sizes; (void)n_in; (void)out_size;
    const float* x = (const float*)d_in[0];
    float* out = (float*)d_out;

    static cudaStream_t st[3] = {0, 0, 0};
    static cudaEvent_t evRoot = 0, evPool = 0, evDone[3] = {0, 0, 0};
    if (!st[0]) {
        for (int i = 0; i < 3; i++)
            cudaStreamCreateWithFlags(&st[i], cudaStreamNonBlocking);
        cudaEventCreateWithFlags(&evRoot, cudaEventDisableTiming);
        cudaEventCreateWithFlags(&evPool, cudaEventDisableTiming);
        for (int i = 0; i < 3; i++)
            cudaEventCreateWithFlags(&evDone[i], cudaEventDisableTiming);
    }

    cudaFuncSetAttribute(routing_fused_kernel, cudaFuncAttributeMaxDynamicSharedMemorySize, 96*1024);
    cudaFuncSetAttribute(prim_mma_kernel, cudaFuncAttributeMaxDynamicSharedMemorySize,
                         GSMEM0 + 10368*4);

    //                src  H  k1 H1  kp Hp  S    R      K   iw br   yo       ko    wo       po      uo      dwto
    BranchCfg b1 = {   2,  7, 3,  5,  3, 2,  4,  128,  1152,  1, 0, 0,       0,    0,       0,      0,      0      };
    BranchCfg b2 = {   1, 14, 5, 10,  5, 3,  9,  288,  3200,  6, 1, 819200,  1152, 294912,  262144, 262144, 163840 };
    BranchCfg b3 = {   0, 28, 9, 20,  9, 6, 36, 1152, 10368, 11, 2, 4096000, 4352, 1114112, 851968, 851968, 532480 };

    cudaEventRecord(evRoot, 0);
    for (int i = 0; i < 3; i++) cudaStreamWaitEvent(st[i], evRoot, 0);

    pool2_kernel<<<(BATCH*14*14 + 255)/256, 256, 0, st[1]>>>(x);
    cudaEventRecord(evPool, st[1]);
    cudaStreamWaitEvent(st[0], evPool, 0);
    pool1_kernel<<<(BATCH*7*7 + 255)/256, 256, 0, st[0]>>>();

    run_branch(b3, d_in, x, st[2]);
    run_branch(b2, d_in, x, st[1]);
    run_branch(b1, d_in, x, st[0]);

    for (int i = 0; i < 3; i++) {
        cudaEventRecord(evDone[i], st[i]);
        cudaStreamWaitEvent(0, evDone[i], 0);
    }
    final_kernel<<<1, 256>>>(out);
}

// round 13
// speedup vs baseline: 1.2800x; 1.2800x over previous
#include <cuda_runtime.h>
#include <cuda_fp16.h>
#include <math.h>
#include <stdint.h>

#define BATCH 256
#define NCLS  10
#define CC    128
#define OCH   256

// GEMM tiling: KC=32, pure fp16 single pass (Ah, Bh)
#define TSTRIDE 40                // fp16 elems per smem row (80B)
#define TILEB   (128*TSTRIDE*2)   // 10240 B per 128x32 fp16 tile
#define STAGEB  (2*TILEB)         // Ah,Bh = 20480 B
#define GSMEM0  (2*STAGEB)        // double buffered = 40960 B (+ ktab)

// ---------------- static device scratch, per-branch offsets ----------------
__device__ float g_x2[BATCH*14*14];
__device__ float g_x1[BATCH*7*7];
__device__ float g_y [17203200];
__device__ float g_mean[3*CC];
__device__ float g_rstd[3*CC];
__device__ float g_bnp[3*CC*8*2];
__device__ float g_badj[3*OCH];
__device__ int   g_ktab[14720];
__device__ __half g_wh[3768320];
__device__ float g_dwt[2007040];            // transposed routing weights [n][r][o][i]
__device__ float g_p [3211264];
__device__ float g_u [3211264];
__device__ float g_len[3*BATCH*NCLS];

// ---------------- PTX helpers ----------------
__device__ __forceinline__ uint32_t smem_u32(const void* p) {
    uint32_t a;
    asm("{ .reg .u64 t; cvta.to.shared.u64 t, %1; cvt.u32.u64 %0, t; }" : "=r"(a) : "l"(p));
    return a;
}
#define CP_ASYNC16(dst, src) \
    asm volatile("cp.async.ca.shared.global [%0], [%1], 16;" :: "r"(dst), "l"(src) : "memory")
#define CP_COMMIT() asm volatile("cp.async.commit_group;" ::: "memory")
#define CP_WAIT0()  asm volatile("cp.async.wait_group 0;" ::: "memory")

__device__ __forceinline__ void ldmx4(uint32_t addr, uint32_t& r0, uint32_t& r1,
                                      uint32_t& r2, uint32_t& r3) {
    asm volatile("ldmatrix.sync.aligned.m8n8.x4.shared.b16 {%0,%1,%2,%3}, [%4];"
                 : "=r"(r0), "=r"(r1), "=r"(r2), "=r"(r3) : "r"(addr));
}
__device__ __forceinline__ void mma16816(float* c, const uint32_t* a, uint32_t b0, uint32_t b1) {
    asm volatile(
        "mma.sync.aligned.m16n8k16.row.col.f32.f16.f16.f32 "
        "{%0,%1,%2,%3}, {%4,%5,%6,%7}, {%8,%9}, {%0,%1,%2,%3};"
        : "+f"(c[0]), "+f"(c[1]), "+f"(c[2]), "+f"(c[3])
        : "r"(a[0]), "r"(a[1]), "r"(a[2]), "r"(a[3]), "r"(b0), "r"(b1));
}

// ---------------- pooling ----------------
__global__ void pool2_kernel(const float* __restrict__ img) {
    int idx = blockIdx.x*blockDim.x + threadIdx.x;
    if (idx >= BATCH*14*14) return;
    int j = idx % 14, i = (idx/14) % 14, b = idx/196;
    const float* p = img + b*784;
    g_x2[idx] = 0.25f*(p[(2*i)*28+2*j] + p[(2*i)*28+2*j+1]
                     + p[(2*i+1)*28+2*j] + p[(2*i+1)*28+2*j+1]);
}
__global__ void pool1_kernel() {
    int idx = blockIdx.x*blockDim.x + threadIdx.x;
    if (idx >= BATCH*7*7) return;
    int j = idx % 7, i = (idx/7) % 7, b = idx/49;
    const float* p = g_x2 + b*196;
    g_x1[idx] = 0.25f*(p[(2*i)*14+2*j] + p[(2*i)*14+2*j+1]
                     + p[(2*i+1)*14+2*j] + p[(2*i+1)*14+2*j+1]);
}

// ---------------- conv stage A: 8 groups x 16 channels per image ----------------
template<int K1, int H, int H1>
__global__ __launch_bounds__(256) void convA_smem(const float* __restrict__ xin_ext, int src,
                                                  const float* __restrict__ w,
                                                  const float* __restrict__ bias,
                                                  size_t yo)
{
    __shared__ float s_in[H*H];
    __shared__ float s_w[16*K1*K1];
    int b = blockIdx.x;
    int c0 = blockIdx.y * 16;
    int tid = threadIdx.x;
    const float* xin = (src == 0) ? xin_ext : (src == 1 ? g_x2 : g_x1);
    const float* ip = xin + b*H*H;
    for (int i = tid; i < H*H; i += 256) s_in[i] = ip[i];
    for (int i = tid; i < 16*K1*K1; i += 256) s_w[i] = w[c0*K1*K1 + i];
    __syncthreads();

    for (int pair = tid; pair < 16*H1; pair += 256) {
        int cl = pair & 15, oy = pair >> 4;
        int c = c0 + cl;
        float bv = __ldg(&bias[c]);
        float acc[H1];
#pragma unroll
        for (int ox = 0; ox < H1; ox++) acc[ox] = bv;
        const float* wc = s_w + cl*K1*K1;
#pragma unroll
        for (int ky = 0; ky < K1; ky++) {
            float row[H1 + K1 - 1];
            const float* rp = s_in + (oy + ky)*H;
#pragma unroll
            for (int x = 0; x < H1 + K1 - 1; x++) row[x] = rp[x];
#pragma unroll
            for (int kx = 0; kx < K1; kx++) {
                float wv = wc[ky*K1 + kx];
#pragma unroll
                for (int ox = 0; ox < H1; ox++)
                    acc[ox] = fmaf(wv, row[ox + kx], acc[ox]);
            }
        }
        float* op = g_y + yo + ((size_t)(b*CC + c)*H1 + oy)*H1;
#pragma unroll
        for (int ox = 0; ox < H1; ox++) op[ox] = fmaxf(acc[ox], 0.f);
    }
}

// ---------------- batchnorm stats: two-phase ----------------
__global__ void bn_partial_kernel(int HW, size_t yo, int br) {
    int c = blockIdx.x, sl = blockIdx.y;
    int tid = threadIdx.x;
    const float* yb = g_y + yo;
    float s = 0.f, s2 = 0.f;
    int total = 32*HW;
    for (int i = tid; i < total; i += 256) {
        int b = sl*32 + i/HW;
        int hw = i - (i/HW)*HW;
        float v = yb[(size_t)(b*CC + c)*HW + hw];
        s += v; s2 += v*v;
    }
#pragma unroll
    for (int off = 16; off; off >>= 1) {
        s  += __shfl_xor_sync(0xffffffffu, s,  off);
        s2 += __shfl_xor_sync(0xffffffffu, s2, off);
    }
    __shared__ float rs[8], rq[8];
    if ((tid & 31) == 0) { rs[tid>>5] = s; rq[tid>>5] = s2; }
    __syncthreads();
    if (tid == 0) {
        float a = 0.f, b2 = 0.f;
#pragma unroll
        for (int w = 0; w < 8; w++) { a += rs[w]; b2 += rq[w]; }
        g_bnp[((br*CC + c)*8 + sl)*2 + 0] = a;
        g_bnp[((br*CC + c)*8 + sl)*2 + 1] = b2;
    }
}
__global__ void bn_final_kernel(int HW, int br) {
    int c = threadIdx.x;
    float s = 0.f, s2 = 0.f;
#pragma unroll
    for (int sl = 0; sl < 8; sl++) {
        s  += g_bnp[((br*CC + c)*8 + sl)*2 + 0];
        s2 += g_bnp[((br*CC + c)*8 + sl)*2 + 1];
    }
    float N = (float)(BATCH*HW);
    float m = s / N;
    float var = s2 / N - m*m;
    g_mean[br*CC + c] = m;
    g_rstd[br*CC + c] = rsqrtf(var + 1e-5f);
}

// ---------------- prep ----------------
__global__ void prep_ktab_kernel(int K, int kp, int H1, size_t ko) {
    int kidx = blockIdx.x*blockDim.x + threadIdx.x;
    if (kidx >= K) return;
    int kk2 = kp*kp;
    int ic = kidx / kk2;
    int rem = kidx - ic*kk2;
    int off = ic*H1*H1 + (rem/kp)*H1 + (rem % kp);
    g_ktab[ko + kidx] = (ic << 20) | off;
}
__global__ void prep_w_kernel(const float* __restrict__ pw, int K, size_t wo,
                              size_t ko, int br) {
    int idx = blockIdx.x*blockDim.x + threadIdx.x;
    if (idx >= OCH*K) return;
    int k = idx - (idx/K)*K;
    int c = g_ktab[ko + k] >> 20;
    float v = pw[idx] * g_rstd[br*CC + c];
    g_wh[wo + idx] = __float2half_rn(v);
}
__global__ void prep_badj_kernel(const float* __restrict__ pw,
                                 const float* __restrict__ pb,
                                 int K, size_t ko, int br) {
    int oc = blockIdx.x;
    int tid = threadIdx.x;
    float s = 0.f;
    for (int k = tid; k < K; k += 256) {
        int c = g_ktab[ko + k] >> 20;
        s += pw[(size_t)oc*K + k] * g_mean[br*CC + c] * g_rstd[br*CC + c];
    }
#pragma unroll
    for (int off = 16; off; off >>= 1) s += __shfl_xor_sync(0xffffffffu, s, off);
    __shared__ float rs[8];
    if ((tid & 31) == 0) rs[tid>>5] = s;
    __syncthreads();
    if (tid == 0) {
        float a = 0.f;
#pragma unroll
        for (int w = 0; w < 8; w++) a += rs[w];
        g_badj[br*OCH + oc] = pb[oc] - a;
    }
}
// transpose routing weights: dwt[n][r][o][i] = dw[n][r][i][o]
__global__ void prep_dwt_kernel(const float* __restrict__ dw, int R, size_t dwto) {
    int idx = blockIdx.x*blockDim.x + threadIdx.x;
    if (idx >= NCLS*R*128) return;
    int i = idx & 7;
    int o = (idx >> 3) & 15;
    int nr = idx >> 7;
    g_dwt[dwto + idx] = dw[(size_t)nr*128 + i*16 + o];
}

// ---------------- prim conv GEMM: inline im2col + pure fp16 mma ----------------
__device__ __forceinline__ void load_B(uint32_t sb, int buf, int n0, int kc, int K,
                                       size_t wo, int tid)
{
    uint32_t dst0 = sb + buf*STAGEB + TILEB;
#pragma unroll
    for (int i = 0; i < 2; i++) {
        int q = tid + i*256;
        int row = q >> 2, ch = q & 3;
        const __half* src = g_wh + wo + (size_t)(n0+row)*K + kc + ch*8;
        CP_ASYNC16(dst0 + row*(TSTRIDE*2) + ch*16, src);
    }
}
__device__ __forceinline__ void gather_A(const float* __restrict__ yb,
                                         const int* rowbase, const int* s_kt,
                                         int kc, int lane, float* f)
{
    int off = s_kt[kc + lane];
#pragma unroll
    for (int j = 0; j < 16; j++) f[j] = yb[rowbase[j] + off];
}
__device__ __forceinline__ void convert_sts_A(char* smem, int buf,
                                              int wid, int lane, const float* f)
{
    char* base = smem + buf*STAGEB + (wid*16)*(TSTRIDE*2) + lane*2;
#pragma unroll
    for (int j = 0; j < 16; j++) {
        *(__half*)(base + j*(TSTRIDE*2)) = __float2half_rn(f[j]);
    }
}

__global__ __launch_bounds__(256) void prim_mma_kernel(int S, int Hp, int H1, int K,
                                                       size_t yo, size_t ko,
                                                       size_t wo, size_t po, int br)
{
    extern __shared__ char smem[];
    int* s_kt = (int*)(smem + GSMEM0);
    uint32_t sb = smem_u32(smem);
    int tid = threadIdx.x, wid = tid >> 5, lane = tid & 31;
    int n0 = (blockIdx.x & 1) << 7;
    int m0 = (int)(blockIdx.x >> 1) << 7;

    for (int k = tid; k < K; k += 256) s_kt[k] = g_ktab[ko + k] & 0xFFFFF;

    int rowbase[16];
#pragma unroll
    for (int j = 0; j < 16; j++) {
        int m = m0 + wid*16 + j;
        int b = m / S, s = m - b*S;
        int oy = s / Hp, ox = s - oy*Hp;
        rowbase[j] = b*CC*H1*H1 + (oy*2)*H1 + ox*2;
    }
    __syncthreads();

    const float* yb = g_y + yo;

    int wm = (wid & 3) << 5;
    int wn = (wid >> 2) << 6;

    float acc[2][8][4];
#pragma unroll
    for (int mt = 0; mt < 2; mt++)
#pragma unroll
        for (int nb = 0; nb < 8; nb++)
#pragma unroll
            for (int j = 0; j < 4; j++) acc[mt][nb][j] = 0.f;

    int nch = K >> 5;

    load_B(sb, 0, n0, 0, K, wo, tid);
    CP_COMMIT();
    {
        float f[16];
        gather_A(yb, rowbase, s_kt, 0, lane, f);
        convert_sts_A(smem, 0, wid, lane, f);
    }
    CP_WAIT0();
    __syncthreads();

    uint32_t aLaneOff = (uint32_t)((lane & 15)*(TSTRIDE*2) + (lane >> 4)*16);
    uint32_t bLaneOff = (uint32_t)((((lane >> 3) & 3)*8 + (lane & 7))*(TSTRIDE*2));

    for (int c = 0; c < nch; c++) {
        int p = c & 1, q = p ^ 1;
        float f[16];
        if (c + 1 < nch) {
            load_B(sb, q, n0, (c + 1) << 5, K, wo, tid);
            CP_COMMIT();
            gather_A(yb, rowbase, s_kt, (c + 1) << 5, lane, f);
        }

        uint32_t st = sb + p*STAGEB;
#pragma unroll
        for (int kk = 0; kk < 2; kk++) {
            uint32_t ah[2][4];
#pragma unroll
            for (int mt = 0; mt < 2; mt++)
                ldmx4(st + (wm + mt*16)*(TSTRIDE*2) + kk*32 + aLaneOff,
                      ah[mt][0], ah[mt][1], ah[mt][2], ah[mt][3]);
            uint32_t bh[8][2];
#pragma unroll
            for (int g = 0; g < 2; g++)
#pragma unroll
                for (int kh = 0; kh < 2; kh++) {
                    uint32_t r0, r1, r2, r3;
                    ldmx4(st + TILEB + (wn + g*32)*(TSTRIDE*2) + kk*32 + kh*16 + bLaneOff,
                          r0, r1, r2, r3);
                    bh[g*4+0][kh] = r0; bh[g*4+1][kh] = r1;
                    bh[g*4+2][kh] = r2; bh[g*4+3][kh] = r3;
                }
#pragma unroll
            for (int mt = 0; mt < 2; mt++)
#pragma unroll
                for (int nb = 0; nb < 8; nb++)
                    mma16816(acc[mt][nb], ah[mt], bh[nb][0], bh[nb][1]);
        }

        if (c + 1 < nch) {
            convert_sts_A(smem, q, wid, lane, f);
            CP_WAIT0();
        }
        __syncthreads();
    }

    int gr = lane >> 2, tc = lane & 3;
    float* gp = g_p + po;
    const float* badj = g_badj + br*OCH;
#pragma unroll
    for (int mt = 0; mt < 2; mt++) {
        int mA = m0 + wm + mt*16 + gr;
        int mB = mA + 8;
#pragma unroll
        for (int nb = 0; nb < 8; nb++) {
            int oc = n0 + wn + nb*8 + tc*2;
            float bias0 = badj[oc], bias1 = badj[oc+1];
            float2 vA = make_float2(acc[mt][nb][0] + bias0, acc[mt][nb][1] + bias1);
            float2 vB = make_float2(acc[mt][nb][2] + bias0, acc[mt][nb][3] + bias1);
            *reinterpret_cast<float2*>(gp + (size_t)mA*OCH + oc) = vA;
            *reinterpret_cast<float2*>(gp + (size_t)mB*OCH + oc) = vB;
        }
    }
}

// ---------------- squash primary capsules (coalesced) ----------------
__global__ void squash_u_kernel(int S, int R, size_t po, size_t uo) {
    int idx = blockIdx.x*blockDim.x + threadIdx.x;
    if (idx >= BATCH*R) return;
    int c32 = idx & 31;
    int bs  = idx >> 5;
    int b = bs / S, s = bs - b*S;
    const float* pp = g_p + po + (size_t)bs*OCH + c32;
    float t[8]; float sn = 0.f;
#pragma unroll
    for (int i = 0; i < 8; i++) {
        t[i] = pp[i*32];
        sn += t[i]*t[i];
    }
    float scale = sn/(1.f + sn) * rsqrtf(sn + 1e-12f);
    int r = c32*S + s;
    float* up = g_u + uo + ((size_t)b*R + r)*8;
#pragma unroll
    for (int i = 0; i < 8; i++)
        up[i] = t[i]*scale;
}

// ---------------- fused priors + dynamic routing (1 batch per CTA) ----------------
__global__ void routing_fused_kernel(int R, int br, size_t uo, size_t dwto) {
    int b = blockIdx.x, n = blockIdx.y;
    extern __shared__ float sm[];
    float* P    = sm;
    float* blog = P + R*16;
    float* wred = blog + R;
    float* vv   = wred + 128;
    float* sred = vv + 16;
    float* scal = sred + 8;

    int tid = threadIdx.x;
    // P build: thread per (r,o). Lanes with consecutive o read contiguous
    // 512B spans of dwt (coalesced float4 pairs); u loads broadcast per half-warp.
    for (int idx = tid; idx < R*16; idx += 256) {
        int r = idx >> 4, o = idx & 15;
        const float4* up4 = reinterpret_cast<const float4*>(g_u + uo + ((size_t)b*R + r)*8);
        float4 u0 = up4[0], u1 = up4[1];
        const float4* wt = reinterpret_cast<const float4*>(g_dwt + dwto + ((size_t)n*R + r)*128) + o*2;
        float4 wa = wt[0], wb = wt[1];
        P[idx] = u0.x*wa.x + u0.y*wa.y + u0.z*wa.z + u0.w*wa.w
               + u1.x*wb.x + u1.y*wb.y + u1.z*wb.z + u1.w*wb.w;
    }
    for (int r = tid; r < R; r += 256) blog[r] = 0.f;
    __syncthreads();

    for (int it = 0; it < 3; it++) {
        float mx = -1e30f;
        for (int r = tid; r < R; r += 256) mx = fmaxf(mx, blog[r]);
#pragma unroll
        for (int off = 16; off; off >>= 1)
            mx = fmaxf(mx, __shfl_xor_sync(0xffffffffu, mx, off));
        if ((tid & 31) == 0) sred[tid >> 5] = mx;
        __syncthreads();
        if (tid == 0) {
            float m = sred[0];
            for (int w2 = 1; w2 < 8; w2++) m = fmaxf(m, sred[w2]);
            scal[0] = m;
        }
        __syncthreads();
        float gmax = scal[0];
        float se = 0.f;
        for (int r = tid; r < R; r += 256) se += expf(blog[r] - gmax);
#pragma unroll
        for (int off = 16; off; off >>= 1)
            se += __shfl_xor_sync(0xffffffffu, se, off);
        if ((tid & 31) == 0) sred[tid >> 5] = se;
        __syncthreads();
        if (tid == 0) {
            float s = 0.f;
            for (int w2 = 0; w2 < 8; w2++) s += sred[w2];
            scal[1] = 1.f/s;
        }
        __syncthreads();
        float isum = scal[1];
        float acc[16];
#pragma unroll
        for (int o = 0; o < 16; o++) acc[o] = 0.f;
        for (int r = tid; r < R; r += 256) {
            float c = expf(blog[r] - gmax)*isum;
            const float* pr = P + r*16;
#pragma unroll
            for (int o = 0; o < 16; o++) acc[o] += c*pr[o];
        }
#pragma unroll
        for (int o = 0; o < 16; o++) {
            float v = acc[o];
#pragma unroll
            for (int off = 16; off; off >>= 1)
                v += __shfl_xor_sync(0xffffffffu, v, off);
            acc[o] = v;
        }
        if ((tid & 31) == 0)
#pragma unroll
            for (int o = 0; o < 16; o++) wred[(tid >> 5)*16 + o] = acc[o];
        __syncthreads();
        if (tid == 0) {
            float s16[16]; float sn = 0.f;
#pragma unroll
            for (int o = 0; o < 16; o++) {
                float s = 0.f;
                for (int w2 = 0; w2 < 8; w2++) s += wred[w2*16 + o];
                s16[o] = s; sn += s*s;
            }
            float sc = sn/(1.f + sn) * rsqrtf(sn + 1e-12f);
#pragma unroll
            for (int o = 0; o < 16; o++) vv[o] = s16[o]*sc;
        }
        __syncthreads();
        if (it < 2) {
            for (int r = tid; r < R; r += 256) {
                const float* pr = P + r*16;
                float d = 0.f;
#pragma unroll
                for (int o = 0; o < 16; o++) d += pr[o]*vv[o];
                blog[r] += d;
            }
            __syncthreads();
        }
    }
    if (tid == 0) {
        float s = 0.f;
#pragma unroll
        for (int o = 0; o < 16; o++) s += vv[o]*vv[o];
        g_len[br*BATCH*NCLS + b*NCLS + n] = sqrtf(s + 1e-12f);
    }
}

// ---------------- final ----------------
__global__ void final_kernel(float* __restrict__ out) {
    int b = blockIdx.x*blockDim.x + threadIdx.x;
    if (b >= BATCH) return;
    float l[NCLS]; float mx = -1e30f;
#pragma unroll
    for (int n = 0; n < NCLS; n++) {
        l[n] = g_len[0*BATCH*NCLS + b*NCLS + n]
             + g_len[1*BATCH*NCLS + b*NCLS + n]
             + g_len[2*BATCH*NCLS + b*NCLS + n];
        mx = fmaxf(mx, l[n]);
    }
    float s = 0.f;
#pragma unroll
    for (int n = 0; n < NCLS; n++) { l[n] = expf(l[n] - mx); s += l[n]; }
    float inv = 1.f/s;
#pragma unroll
    for (int n = 0; n < NCLS; n++) out[b*NCLS + n] = l[n]*inv;
}

// ---------------- host driver ----------------
struct BranchCfg {
    int src;
    int H, k1, H1, kp, Hp, S, R, K;
    int iw, br;
    size_t yo, ko, wo, po, uo, dwto;
};

static void run_branch(const BranchCfg& c, void* const* d_in, const float* x,
                       cudaStream_t st)
{
    const float* cw = (const float*)d_in[c.iw + 0];
    const float* cb = (const float*)d_in[c.iw + 1];
    const float* pw = (const float*)d_in[c.iw + 2];
    const float* pb = (const float*)d_in[c.iw + 3];
    const float* dw = (const float*)d_in[c.iw + 4];

    int HW = c.H1*c.H1;
    prep_ktab_kernel<<<(c.K + 255)/256, 256, 0, st>>>(c.K, c.kp, c.H1, c.ko);
    prep_dwt_kernel<<<(NCLS*c.R*128 + 255)/256, 256, 0, st>>>(dw, c.R, c.dwto);
    dim3 cgrid(BATCH, 8);
    if (c.k1 == 3)      convA_smem<3, 7, 5  ><<<cgrid, 256, 0, st>>>(x, c.src, cw, cb, c.yo);
    else if (c.k1 == 5) convA_smem<5, 14, 10><<<cgrid, 256, 0, st>>>(x, c.src, cw, cb, c.yo);
    else                convA_smem<9, 28, 20><<<cgrid, 256, 0, st>>>(x, c.src, cw, cb, c.yo);
    bn_partial_kernel<<<dim3(CC, 8), 256, 0, st>>>(HW, c.yo, c.br);
    bn_final_kernel<<<1, CC, 0, st>>>(HW, c.br);

    prep_w_kernel<<<(OCH*c.K + 255)/256, 256, 0, st>>>(pw, c.K, c.wo, c.ko, c.br);
    prep_badj_kernel<<<OCH, 256, 0, st>>>(pw, pb, c.K, c.ko, c.br);

    int M = BATCH*c.S;
    int gsmem = GSMEM0 + c.K*4;
    prim_mma_kernel<<<2*(M/128), 256, gsmem, st>>>(c.S, c.Hp, c.H1, c.K,
                                                   c.yo, c.ko, c.wo, c.po, c.br);

    squash_u_kernel<<<(BATCH*c.R + 255)/256, 256, 0, st>>>(c.S, c.R, c.po, c.uo);

    int smemR = (c.R*17 + 128 + 16 + 8 + 2)*(int)sizeof(float);
    dim3 rgrid(BATCH, NCLS);
    routing_fused_kernel<<<rgrid, 256, smemR, st>>>(c.R, c.br, c.uo, c.dwto);
}

extern "C" void kernel_launch(void* const* d_in, const int* in_sizes, int n_in,
                              void* d_out, int out_size)
{
    (void)in_sizes; (void)n_in; (void)out_size;
    const float* x = (const float*)d_in[0];
    float* out = (float*)d_out;

    static cudaStream_t st[3] = {0, 0, 0};
    static cudaEvent_t evRoot = 0, evPool = 0, evDone[3] = {0, 0, 0};
    if (!st[0]) {
        for (int i = 0; i < 3; i++)
            cudaStreamCreateWithFlags(&st[i], cudaStreamNonBlocking);
        cudaEventCreateWithFlags(&evRoot, cudaEventDisableTiming);
        cudaEventCreateWithFlags(&evPool, cudaEventDisableTiming);
        for (int i = 0; i < 3; i++)
            cudaEventCreateWithFlags(&evDone[i], cudaEventDisableTiming);
    }

    cudaFuncSetAttribute(routing_fused_kernel, cudaFuncAttributeMaxDynamicSharedMemorySize, 96*1024);
    cudaFuncSetAttribute(prim_mma_kernel, cudaFuncAttributeMaxDynamicSharedMemorySize,
                         GSMEM0 + 10368*4);

    //                src  H  k1 H1  kp Hp  S    R      K   iw br   yo       ko    wo       po      uo      dwto
    BranchCfg b1 = {   2,  7, 3,  5,  3, 2,  4,  128,  1152,  1, 0, 0,       0,    0,       0,      0,      0      };
    BranchCfg b2 = {   1, 14, 5, 10,  5, 3,  9,  288,  3200,  6, 1, 819200,  1152, 294912,  262144, 262144, 163840 };
    BranchCfg b3 = {   0, 28, 9, 20,  9, 6, 36, 1152, 10368, 11, 2, 4096000, 4352, 1114112, 851968, 851968, 532480 };

    cudaEventRecord(evRoot, 0);
    for (int i = 0; i < 3; i++) cudaStreamWaitEvent(st[i], evRoot, 0);

    pool2_kernel<<<(BATCH*14*14 + 255)/256, 256, 0, st[1]>>>(x);
    cudaEventRecord(evPool, st[1]);
    cudaStreamWaitEvent(st[0], evPool, 0);
    pool1_kernel<<<(BATCH*7*7 + 255)/256, 256, 0, st[0]>>>();

    run_branch(b3, d_in, x, st[2]);
    run_branch(b2, d_in, x, st[1]);
    run_branch(b1, d_in, x, st[0]);

    for (int i = 0; i < 3; i++) {
        cudaEventRecord(evDone[i], st[i]);
        cudaStreamWaitEvent(0, evDone[i], 0);
    }
    final_kernel<<<1, 256>>>(out);
}

// round 14
// speedup vs baseline: 1.2959x; 1.0124x over previous
#include <cuda_runtime.h>
#include <cuda_fp16.h>
#include <math.h>
#include <stdint.h>

#define BATCH 256
#define NCLS  10
#define CC    128
#define OCH   256

// GEMM tiling: KC=32, pure fp16 single pass (Ah, Bh)
#define TSTRIDE 40                // fp16 elems per smem row (80B)
#define TILEB   (128*TSTRIDE*2)   // 10240 B per 128x32 fp16 tile
#define STAGEB  (2*TILEB)         // Ah,Bh = 20480 B
#define GSMEM0  (2*STAGEB)        // double buffered = 40960 B (+ ktab)

// ---------------- static device scratch, per-branch offsets ----------------
__device__ float g_x2[BATCH*14*14];
__device__ float g_x1[BATCH*7*7];
__device__ float g_y [17203200];
__device__ float g_mean[3*CC];
__device__ float g_rstd[3*CC];
__device__ float g_bnp[3*CC*8*2];
__device__ float g_badj[3*OCH];
__device__ int   g_ktab[14720];
__device__ __half g_wh[3768320];
__device__ float g_dwt[2007040];            // transposed routing weights [n][r][o][i]
__device__ float g_p [3211264];
__device__ float g_u [3211264];
__device__ float g_len[3*BATCH*NCLS];

// ---------------- PTX helpers ----------------
__device__ __forceinline__ uint32_t smem_u32(const void* p) {
    uint32_t a;
    asm("{ .reg .u64 t; cvta.to.shared.u64 t, %1; cvt.u32.u64 %0, t; }" : "=r"(a) : "l"(p));
    return a;
}
#define CP_ASYNC16(dst, src) \
    asm volatile("cp.async.ca.shared.global [%0], [%1], 16;" :: "r"(dst), "l"(src) : "memory")
#define CP_COMMIT() asm volatile("cp.async.commit_group;" ::: "memory")
#define CP_WAIT0()  asm volatile("cp.async.wait_group 0;" ::: "memory")

__device__ __forceinline__ void ldmx4(uint32_t addr, uint32_t& r0, uint32_t& r1,
                                      uint32_t& r2, uint32_t& r3) {
    asm volatile("ldmatrix.sync.aligned.m8n8.x4.shared.b16 {%0,%1,%2,%3}, [%4];"
                 : "=r"(r0), "=r"(r1), "=r"(r2), "=r"(r3) : "r"(addr));
}
__device__ __forceinline__ void mma16816(float* c, const uint32_t* a, uint32_t b0, uint32_t b1) {
    asm volatile(
        "mma.sync.aligned.m16n8k16.row.col.f32.f16.f16.f32 "
        "{%0,%1,%2,%3}, {%4,%5,%6,%7}, {%8,%9}, {%0,%1,%2,%3};"
        : "+f"(c[0]), "+f"(c[1]), "+f"(c[2]), "+f"(c[3])
        : "r"(a[0]), "r"(a[1]), "r"(a[2]), "r"(a[3]), "r"(b0), "r"(b1));
}

// ---------------- pooling ----------------
__global__ void pool2_kernel(const float* __restrict__ img) {
    int idx = blockIdx.x*blockDim.x + threadIdx.x;
    if (idx >= BATCH*14*14) return;
    int j = idx % 14, i = (idx/14) % 14, b = idx/196;
    const float* p = img + b*784;
    g_x2[idx] = 0.25f*(p[(2*i)*28+2*j] + p[(2*i)*28+2*j+1]
                     + p[(2*i+1)*28+2*j] + p[(2*i+1)*28+2*j+1]);
}
__global__ void pool1_kernel() {
    int idx = blockIdx.x*blockDim.x + threadIdx.x;
    if (idx >= BATCH*7*7) return;
    int j = idx % 7, i = (idx/7) % 7, b = idx/49;
    const float* p = g_x2 + b*196;
    g_x1[idx] = 0.25f*(p[(2*i)*14+2*j] + p[(2*i)*14+2*j+1]
                     + p[(2*i+1)*14+2*j] + p[(2*i+1)*14+2*j+1]);
}

// ---------------- conv stage A: 8 groups x 16 channels per image ----------------
template<int K1, int H, int H1>
__global__ __launch_bounds__(256) void convA_smem(const float* __restrict__ xin_ext, int src,
                                                  const float* __restrict__ w,
                                                  const float* __restrict__ bias,
                                                  size_t yo)
{
    __shared__ float s_in[H*H];
    __shared__ float s_w[16*K1*K1];
    int b = blockIdx.x;
    int c0 = blockIdx.y * 16;
    int tid = threadIdx.x;
    const float* xin = (src == 0) ? xin_ext : (src == 1 ? g_x2 : g_x1);
    const float* ip = xin + b*H*H;
    for (int i = tid; i < H*H; i += 256) s_in[i] = ip[i];
    for (int i = tid; i < 16*K1*K1; i += 256) s_w[i] = w[c0*K1*K1 + i];
    __syncthreads();

    for (int pair = tid; pair < 16*H1; pair += 256) {
        int cl = pair & 15, oy = pair >> 4;
        int c = c0 + cl;
        float bv = __ldg(&bias[c]);
        float acc[H1];
#pragma unroll
        for (int ox = 0; ox < H1; ox++) acc[ox] = bv;
        const float* wc = s_w + cl*K1*K1;
#pragma unroll
        for (int ky = 0; ky < K1; ky++) {
            float row[H1 + K1 - 1];
            const float* rp = s_in + (oy + ky)*H;
#pragma unroll
            for (int x = 0; x < H1 + K1 - 1; x++) row[x] = rp[x];
#pragma unroll
            for (int kx = 0; kx < K1; kx++) {
                float wv = wc[ky*K1 + kx];
#pragma unroll
                for (int ox = 0; ox < H1; ox++)
                    acc[ox] = fmaf(wv, row[ox + kx], acc[ox]);
            }
        }
        float* op = g_y + yo + ((size_t)(b*CC + c)*H1 + oy)*H1;
#pragma unroll
        for (int ox = 0; ox < H1; ox++) op[ox] = fmaxf(acc[ox], 0.f);
    }
}

// ---------------- batchnorm stats: two-phase ----------------
__global__ void bn_partial_kernel(int HW, size_t yo, int br) {
    int c = blockIdx.x, sl = blockIdx.y;
    int tid = threadIdx.x;
    const float* yb = g_y + yo;
    float s = 0.f, s2 = 0.f;
    int total = 32*HW;
    for (int i = tid; i < total; i += 256) {
        int b = sl*32 + i/HW;
        int hw = i - (i/HW)*HW;
        float v = yb[(size_t)(b*CC + c)*HW + hw];
        s += v; s2 += v*v;
    }
#pragma unroll
    for (int off = 16; off; off >>= 1) {
        s  += __shfl_xor_sync(0xffffffffu, s,  off);
        s2 += __shfl_xor_sync(0xffffffffu, s2, off);
    }
    __shared__ float rs[8], rq[8];
    if ((tid & 31) == 0) { rs[tid>>5] = s; rq[tid>>5] = s2; }
    __syncthreads();
    if (tid == 0) {
        float a = 0.f, b2 = 0.f;
#pragma unroll
        for (int w = 0; w < 8; w++) { a += rs[w]; b2 += rq[w]; }
        g_bnp[((br*CC + c)*8 + sl)*2 + 0] = a;
        g_bnp[((br*CC + c)*8 + sl)*2 + 1] = b2;
    }
}
__global__ void bn_final_kernel(int HW, int br) {
    int c = threadIdx.x;
    float s = 0.f, s2 = 0.f;
#pragma unroll
    for (int sl = 0; sl < 8; sl++) {
        s  += g_bnp[((br*CC + c)*8 + sl)*2 + 0];
        s2 += g_bnp[((br*CC + c)*8 + sl)*2 + 1];
    }
    float N = (float)(BATCH*HW);
    float m = s / N;
    float var = s2 / N - m*m;
    g_mean[br*CC + c] = m;
    g_rstd[br*CC + c] = rsqrtf(var + 1e-5f);
}

// ---------------- prep ----------------
__global__ void prep_ktab_kernel(int K, int kp, int H1, size_t ko) {
    int kidx = blockIdx.x*blockDim.x + threadIdx.x;
    if (kidx >= K) return;
    int kk2 = kp*kp;
    int ic = kidx / kk2;
    int rem = kidx - ic*kk2;
    int off = ic*H1*H1 + (rem/kp)*H1 + (rem % kp);
    g_ktab[ko + kidx] = (ic << 20) | off;
}
__global__ void prep_w_kernel(const float* __restrict__ pw, int K, size_t wo,
                              size_t ko, int br) {
    int idx = blockIdx.x*blockDim.x + threadIdx.x;
    if (idx >= OCH*K) return;
    int k = idx - (idx/K)*K;
    int c = g_ktab[ko + k] >> 20;
    float v = pw[idx] * g_rstd[br*CC + c];
    g_wh[wo + idx] = __float2half_rn(v);
}
__global__ void prep_badj_kernel(const float* __restrict__ pw,
                                 const float* __restrict__ pb,
                                 int K, size_t ko, int br) {
    int oc = blockIdx.x;
    int tid = threadIdx.x;
    float s = 0.f;
    for (int k = tid; k < K; k += 256) {
        int c = g_ktab[ko + k] >> 20;
        s += pw[(size_t)oc*K + k] * g_mean[br*CC + c] * g_rstd[br*CC + c];
    }
#pragma unroll
    for (int off = 16; off; off >>= 1) s += __shfl_xor_sync(0xffffffffu, s, off);
    __shared__ float rs[8];
    if ((tid & 31) == 0) rs[tid>>5] = s;
    __syncthreads();
    if (tid == 0) {
        float a = 0.f;
#pragma unroll
        for (int w = 0; w < 8; w++) a += rs[w];
        g_badj[br*OCH + oc] = pb[oc] - a;
    }
}
// transpose routing weights: dwt[n][r][o][i] = dw[n][r][i][o]
__global__ void prep_dwt_kernel(const float* __restrict__ dw, int R, size_t dwto) {
    int idx = blockIdx.x*blockDim.x + threadIdx.x;
    if (idx >= NCLS*R*128) return;
    int i = idx & 7;
    int o = (idx >> 3) & 15;
    int nr = idx >> 7;
    g_dwt[dwto + idx] = dw[(size_t)nr*128 + i*16 + o];
}

// ---------------- prim conv GEMM: inline im2col + pure fp16 mma ----------------
__device__ __forceinline__ void load_B(uint32_t sb, int buf, int n0, int kc, int K,
                                       size_t wo, int tid)
{
    uint32_t dst0 = sb + buf*STAGEB + TILEB;
#pragma unroll
    for (int i = 0; i < 2; i++) {
        int q = tid + i*256;
        int row = q >> 2, ch = q & 3;
        const __half* src = g_wh + wo + (size_t)(n0+row)*K + kc + ch*8;
        CP_ASYNC16(dst0 + row*(TSTRIDE*2) + ch*16, src);
    }
}
__device__ __forceinline__ void gather_A(const float* __restrict__ yb,
                                         const int* rowbase, const int* s_kt,
                                         int kc, int lane, float* f)
{
    int off = s_kt[kc + lane];
#pragma unroll
    for (int j = 0; j < 16; j++) f[j] = yb[rowbase[j] + off];
}
__device__ __forceinline__ void convert_sts_A(char* smem, int buf,
                                              int wid, int lane, const float* f)
{
    char* base = smem + buf*STAGEB + (wid*16)*(TSTRIDE*2) + lane*2;
#pragma unroll
    for (int j = 0; j < 16; j++) {
        *(__half*)(base + j*(TSTRIDE*2)) = __float2half_rn(f[j]);
    }
}

__global__ __launch_bounds__(256) void prim_mma_kernel(int S, int Hp, int H1, int K,
                                                       size_t yo, size_t ko,
                                                       size_t wo, size_t po, int br)
{
    extern __shared__ char smem[];
    int* s_kt = (int*)(smem + GSMEM0);
    uint32_t sb = smem_u32(smem);
    int tid = threadIdx.x, wid = tid >> 5, lane = tid & 31;
    int n0 = (blockIdx.x & 1) << 7;
    int m0 = (int)(blockIdx.x >> 1) << 7;

    for (int k = tid; k < K; k += 256) s_kt[k] = g_ktab[ko + k] & 0xFFFFF;

    int rowbase[16];
#pragma unroll
    for (int j = 0; j < 16; j++) {
        int m = m0 + wid*16 + j;
        int b = m / S, s = m - b*S;
        int oy = s / Hp, ox = s - oy*Hp;
        rowbase[j] = b*CC*H1*H1 + (oy*2)*H1 + ox*2;
    }
    __syncthreads();

    const float* yb = g_y + yo;

    int wm = (wid & 3) << 5;
    int wn = (wid >> 2) << 6;

    float acc[2][8][4];
#pragma unroll
    for (int mt = 0; mt < 2; mt++)
#pragma unroll
        for (int nb = 0; nb < 8; nb++)
#pragma unroll
            for (int j = 0; j < 4; j++) acc[mt][nb][j] = 0.f;

    int nch = K >> 5;

    load_B(sb, 0, n0, 0, K, wo, tid);
    CP_COMMIT();
    {
        float f[16];
        gather_A(yb, rowbase, s_kt, 0, lane, f);
        convert_sts_A(smem, 0, wid, lane, f);
    }
    CP_WAIT0();
    __syncthreads();

    uint32_t aLaneOff = (uint32_t)((lane & 15)*(TSTRIDE*2) + (lane >> 4)*16);
    uint32_t bLaneOff = (uint32_t)((((lane >> 3) & 3)*8 + (lane & 7))*(TSTRIDE*2));

    for (int c = 0; c < nch; c++) {
        int p = c & 1, q = p ^ 1;
        float f[16];
        if (c + 1 < nch) {
            load_B(sb, q, n0, (c + 1) << 5, K, wo, tid);
            CP_COMMIT();
            gather_A(yb, rowbase, s_kt, (c + 1) << 5, lane, f);
        }

        uint32_t st = sb + p*STAGEB;
#pragma unroll
        for (int kk = 0; kk < 2; kk++) {
            uint32_t ah[2][4];
#pragma unroll
            for (int mt = 0; mt < 2; mt++)
                ldmx4(st + (wm + mt*16)*(TSTRIDE*2) + kk*32 + aLaneOff,
                      ah[mt][0], ah[mt][1], ah[mt][2], ah[mt][3]);
            uint32_t bh[8][2];
#pragma unroll
            for (int g = 0; g < 2; g++)
#pragma unroll
                for (int kh = 0; kh < 2; kh++) {
                    uint32_t r0, r1, r2, r3;
                    ldmx4(st + TILEB + (wn + g*32)*(TSTRIDE*2) + kk*32 + kh*16 + bLaneOff,
                          r0, r1, r2, r3);
                    bh[g*4+0][kh] = r0; bh[g*4+1][kh] = r1;
                    bh[g*4+2][kh] = r2; bh[g*4+3][kh] = r3;
                }
#pragma unroll
            for (int mt = 0; mt < 2; mt++)
#pragma unroll
                for (int nb = 0; nb < 8; nb++)
                    mma16816(acc[mt][nb], ah[mt], bh[nb][0], bh[nb][1]);
        }

        if (c + 1 < nch) {
            convert_sts_A(smem, q, wid, lane, f);
            CP_WAIT0();
        }
        __syncthreads();
    }

    int gr = lane >> 2, tc = lane & 3;
    float* gp = g_p + po;
    const float* badj = g_badj + br*OCH;
#pragma unroll
    for (int mt = 0; mt < 2; mt++) {
        int mA = m0 + wm + mt*16 + gr;
        int mB = mA + 8;
#pragma unroll
        for (int nb = 0; nb < 8; nb++) {
            int oc = n0 + wn + nb*8 + tc*2;
            float bias0 = badj[oc], bias1 = badj[oc+1];
            float2 vA = make_float2(acc[mt][nb][0] + bias0, acc[mt][nb][1] + bias1);
            float2 vB = make_float2(acc[mt][nb][2] + bias0, acc[mt][nb][3] + bias1);
            *reinterpret_cast<float2*>(gp + (size_t)mA*OCH + oc) = vA;
            *reinterpret_cast<float2*>(gp + (size_t)mB*OCH + oc) = vB;
        }
    }
}

// ---------------- squash primary capsules (coalesced) ----------------
__global__ void squash_u_kernel(int S, int R, size_t po, size_t uo) {
    int idx = blockIdx.x*blockDim.x + threadIdx.x;
    if (idx >= BATCH*R) return;
    int c32 = idx & 31;
    int bs  = idx >> 5;
    int b = bs / S, s = bs - b*S;
    const float* pp = g_p + po + (size_t)bs*OCH + c32;
    float t[8]; float sn = 0.f;
#pragma unroll
    for (int i = 0; i < 8; i++) {
        t[i] = pp[i*32];
        sn += t[i]*t[i];
    }
    float scale = sn/(1.f + sn) * rsqrtf(sn + 1e-12f);
    int r = c32*S + s;
    float* up = g_u + uo + ((size_t)b*R + r)*8;
#pragma unroll
    for (int i = 0; i < 8; i++)
        up[i] = t[i]*scale;
}

// ---------------- fused priors + dynamic routing ----------------
// iter0 softmax is uniform (b=0) -> plain mean; iters 1-2 use unshifted exp
// (blog bounded, softmax shift-invariant) with exp cached in smem.
__global__ void routing_fused_kernel(int R, int br, size_t uo, size_t dwto) {
    int b = blockIdx.x, n = blockIdx.y;
    extern __shared__ float sm[];
    float* P    = sm;            // R*16
    float* blog = P + R*16;      // R
    float* E    = blog + R;      // R
    float* wred = E + R;         // 128
    float* vv   = wred + 128;    // 16
    float* sred = vv + 16;       // 8
    float* scal = sred + 8;      // 2

    int tid = threadIdx.x;
    // P build: thread per (r,o); coalesced dwt float4 pairs
    for (int idx = tid; idx < R*16; idx += 256) {
        int r = idx >> 4, o = idx & 15;
        const float4* up4 = reinterpret_cast<const float4*>(g_u + uo + ((size_t)b*R + r)*8);
        float4 u0 = up4[0], u1 = up4[1];
        const float4* wt = reinterpret_cast<const float4*>(g_dwt + dwto + ((size_t)n*R + r)*128) + o*2;
        float4 wa = wt[0], wb = wt[1];
        P[idx] = u0.x*wa.x + u0.y*wa.y + u0.z*wa.z + u0.w*wa.w
               + u1.x*wb.x + u1.y*wb.y + u1.z*wb.z + u1.w*wb.w;
    }
    __syncthreads();

    float acc[16];

    // ---- iteration 0: uniform coefficients c = 1/R ----
    {
#pragma unroll
        for (int o = 0; o < 16; o++) acc[o] = 0.f;
        for (int r = tid; r < R; r += 256) {
            const float4* pr = reinterpret_cast<const float4*>(P + r*16);
            float4 p0 = pr[0], p1 = pr[1], p2 = pr[2], p3 = pr[3];
            acc[0]+=p0.x; acc[1]+=p0.y; acc[2]+=p0.z; acc[3]+=p0.w;
            acc[4]+=p1.x; acc[5]+=p1.y; acc[6]+=p1.z; acc[7]+=p1.w;
            acc[8]+=p2.x; acc[9]+=p2.y; acc[10]+=p2.z; acc[11]+=p2.w;
            acc[12]+=p3.x; acc[13]+=p3.y; acc[14]+=p3.z; acc[15]+=p3.w;
        }
#pragma unroll
        for (int o = 0; o < 16; o++) {
            float v = acc[o];
#pragma unroll
            for (int off = 16; off; off >>= 1)
                v += __shfl_xor_sync(0xffffffffu, v, off);
            acc[o] = v;
        }
        if ((tid & 31) == 0)
#pragma unroll
            for (int o = 0; o < 16; o++) wred[(tid >> 5)*16 + o] = acc[o];
        __syncthreads();
        if (tid == 0) {
            float invR = 1.f / (float)R;
            float s16[16]; float sn = 0.f;
#pragma unroll
            for (int o = 0; o < 16; o++) {
                float s = 0.f;
                for (int w2 = 0; w2 < 8; w2++) s += wred[w2*16 + o];
                s *= invR;
                s16[o] = s; sn += s*s;
            }
            float sc = sn/(1.f + sn) * rsqrtf(sn + 1e-12f);
#pragma unroll
            for (int o = 0; o < 16; o++) vv[o] = s16[o]*sc;
        }
        __syncthreads();
        // blog was 0 -> blog = dot(P_r, v)
        float v16[16];
#pragma unroll
        for (int o = 0; o < 16; o++) v16[o] = vv[o];
        for (int r = tid; r < R; r += 256) {
            const float4* pr = reinterpret_cast<const float4*>(P + r*16);
            float4 p0 = pr[0], p1 = pr[1], p2 = pr[2], p3 = pr[3];
            float d = p0.x*v16[0]+p0.y*v16[1]+p0.z*v16[2]+p0.w*v16[3]
                    + p1.x*v16[4]+p1.y*v16[5]+p1.z*v16[6]+p1.w*v16[7]
                    + p2.x*v16[8]+p2.y*v16[9]+p2.z*v16[10]+p2.w*v16[11]
                    + p3.x*v16[12]+p3.y*v16[13]+p3.z*v16[14]+p3.w*v16[15];
            blog[r] = d;
        }
        __syncthreads();
    }

    // ---- iterations 1, 2 ----
    for (int it = 1; it < 3; it++) {
        float se = 0.f;
        for (int r = tid; r < R; r += 256) {
            float e = __expf(blog[r]);
            E[r] = e;
            se += e;
        }
#pragma unroll
        for (int off = 16; off; off >>= 1)
            se += __shfl_xor_sync(0xffffffffu, se, off);
        if ((tid & 31) == 0) sred[tid >> 5] = se;
        __syncthreads();
        if (tid == 0) {
            float s = 0.f;
            for (int w2 = 0; w2 < 8; w2++) s += sred[w2];
            scal[0] = 1.f/s;
        }
        __syncthreads();
        float isum = scal[0];
#pragma unroll
        for (int o = 0; o < 16; o++) acc[o] = 0.f;
        for (int r = tid; r < R; r += 256) {
            float c = E[r]*isum;
            const float4* pr = reinterpret_cast<const float4*>(P + r*16);
            float4 p0 = pr[0], p1 = pr[1], p2 = pr[2], p3 = pr[3];
            acc[0]+=c*p0.x; acc[1]+=c*p0.y; acc[2]+=c*p0.z; acc[3]+=c*p0.w;
            acc[4]+=c*p1.x; acc[5]+=c*p1.y; acc[6]+=c*p1.z; acc[7]+=c*p1.w;
            acc[8]+=c*p2.x; acc[9]+=c*p2.y; acc[10]+=c*p2.z; acc[11]+=c*p2.w;
            acc[12]+=c*p3.x; acc[13]+=c*p3.y; acc[14]+=c*p3.z; acc[15]+=c*p3.w;
        }
#pragma unroll
        for (int o = 0; o < 16; o++) {
            float v = acc[o];
#pragma unroll
            for (int off = 16; off; off >>= 1)
                v += __shfl_xor_sync(0xffffffffu, v, off);
            acc[o] = v;
        }
        if ((tid & 31) == 0)
#pragma unroll
            for (int o = 0; o < 16; o++) wred[(tid >> 5)*16 + o] = acc[o];
        __syncthreads();
        if (tid == 0) {
            float s16[16]; float sn = 0.f;
#pragma unroll
            for (int o = 0; o < 16; o++) {
                float s = 0.f;
                for (int w2 = 0; w2 < 8; w2++) s += wred[w2*16 + o];
                s16[o] = s; sn += s*s;
            }
            float sc = sn/(1.f + sn) * rsqrtf(sn + 1e-12f);
#pragma unroll
            for (int o = 0; o < 16; o++) vv[o] = s16[o]*sc;
        }
        __syncthreads();
        if (it < 2) {
            float v16[16];
#pragma unroll
            for (int o = 0; o < 16; o++) v16[o] = vv[o];
            for (int r = tid; r < R; r += 256) {
                const float4* pr = reinterpret_cast<const float4*>(P + r*16);
                float4 p0 = pr[0], p1 = pr[1], p2 = pr[2], p3 = pr[3];
                float d = p0.x*v16[0]+p0.y*v16[1]+p0.z*v16[2]+p0.w*v16[3]
                        + p1.x*v16[4]+p1.y*v16[5]+p1.z*v16[6]+p1.w*v16[7]
                        + p2.x*v16[8]+p2.y*v16[9]+p2.z*v16[10]+p2.w*v16[11]
                        + p3.x*v16[12]+p3.y*v16[13]+p3.z*v16[14]+p3.w*v16[15];
                blog[r] += d;
            }
            __syncthreads();
        }
    }
    if (tid == 0) {
        float s = 0.f;
#pragma unroll
        for (int o = 0; o < 16; o++) s += vv[o]*vv[o];
        g_len[br*BATCH*NCLS + b*NCLS + n] = sqrtf(s + 1e-12f);
    }
}

// ---------------- final ----------------
__global__ void final_kernel(float* __restrict__ out) {
    int b = blockIdx.x*blockDim.x + threadIdx.x;
    if (b >= BATCH) return;
    float l[NCLS]; float mx = -1e30f;
#pragma unroll
    for (int n = 0; n < NCLS; n++) {
        l[n] = g_len[0*BATCH*NCLS + b*NCLS + n]
             + g_len[1*BATCH*NCLS + b*NCLS + n]
             + g_len[2*BATCH*NCLS + b*NCLS + n];
        mx = fmaxf(mx, l[n]);
    }
    float s = 0.f;
#pragma unroll
    for (int n = 0; n < NCLS; n++) { l[n] = expf(l[n] - mx); s += l[n]; }
    float inv = 1.f/s;
#pragma unroll
    for (int n = 0; n < NCLS; n++) out[b*NCLS + n] = l[n]*inv;
}

// ---------------- host driver ----------------
struct BranchCfg {
    int src;
    int H, k1, H1, kp, Hp, S, R, K;
    int iw, br;
    size_t yo, ko, wo, po, uo, dwto;
};

static void run_branch(const BranchCfg& c, void* const* d_in, const float* x,
                       cudaStream_t st)
{
    const float* cw = (const float*)d_in[c.iw + 0];
    const float* cb = (const float*)d_in[c.iw + 1];
    const float* pw = (const float*)d_in[c.iw + 2];
    const float* pb = (const float*)d_in[c.iw + 3];
    const float* dw = (const float*)d_in[c.iw + 4];

    int HW = c.H1*c.H1;
    prep_ktab_kernel<<<(c.K + 255)/256, 256, 0, st>>>(c.K, c.kp, c.H1, c.ko);
    prep_dwt_kernel<<<(NCLS*c.R*128 + 255)/256, 256, 0, st>>>(dw, c.R, c.dwto);
    dim3 cgrid(BATCH, 8);
    if (c.k1 == 3)      convA_smem<3, 7, 5  ><<<cgrid, 256, 0, st>>>(x, c.src, cw, cb, c.yo);
    else if (c.k1 == 5) convA_smem<5, 14, 10><<<cgrid, 256, 0, st>>>(x, c.src, cw, cb, c.yo);
    else                convA_smem<9, 28, 20><<<cgrid, 256, 0, st>>>(x, c.src, cw, cb, c.yo);
    bn_partial_kernel<<<dim3(CC, 8), 256, 0, st>>>(HW, c.yo, c.br);
    bn_final_kernel<<<1, CC, 0, st>>>(HW, c.br);

    prep_w_kernel<<<(OCH*c.K + 255)/256, 256, 0, st>>>(pw, c.K, c.wo, c.ko, c.br);
    prep_badj_kernel<<<OCH, 256, 0, st>>>(pw, pb, c.K, c.ko, c.br);

    int M = BATCH*c.S;
    int gsmem = GSMEM0 + c.K*4;
    prim_mma_kernel<<<2*(M/128), 256, gsmem, st>>>(c.S, c.Hp, c.H1, c.K,
                                                   c.yo, c.ko, c.wo, c.po, c.br);

    squash_u_kernel<<<(BATCH*c.R + 255)/256, 256, 0, st>>>(c.S, c.R, c.po, c.uo);

    int smemR = (c.R*18 + 128 + 16 + 8 + 2)*(int)sizeof(float);
    dim3 rgrid(BATCH, NCLS);
    routing_fused_kernel<<<rgrid, 256, smemR, st>>>(c.R, c.br, c.uo, c.dwto);
}

extern "C" void kernel_launch(void* const* d_in, const int* in_sizes, int n_in,
                              void* d_out, int out_size)
{
    (void)in_sizes; (void)n_in; (void)out_size;
    const float* x = (const float*)d_in[0];
    float* out = (float*)d_out;

    static cudaStream_t st[3] = {0, 0, 0};
    static cudaEvent_t evRoot = 0, evPool = 0, evDone[3] = {0, 0, 0};
    if (!st[0]) {
        for (int i = 0; i < 3; i++)
            cudaStreamCreateWithFlags(&st[i], cudaStreamNonBlocking);
        cudaEventCreateWithFlags(&evRoot, cudaEventDisableTiming);
        cudaEventCreateWithFlags(&evPool, cudaEventDisableTiming);
        for (int i = 0; i < 3; i++)
            cudaEventCreateWithFlags(&evDone[i], cudaEventDisableTiming);
    }

    cudaFuncSetAttribute(routing_fused_kernel, cudaFuncAttributeMaxDynamicSharedMemorySize, 96*1024);
    cudaFuncSetAttribute(prim_mma_kernel, cudaFuncAttributeMaxDynamicSharedMemorySize,
                         GSMEM0 + 10368*4);

    //                src  H  k1 H1  kp Hp  S    R      K   iw br   yo       ko    wo       po      uo      dwto
    BranchCfg b1 = {   2,  7, 3,  5,  3, 2,  4,  128,  1152,  1, 0, 0,       0,    0,       0,      0,      0      };
    BranchCfg b2 = {   1, 14, 5, 10,  5, 3,  9,  288,  3200,  6, 1, 819200,  1152, 294912,  262144, 262144, 163840 };
    BranchCfg b3 = {   0, 28, 9, 20,  9, 6, 36, 1152, 10368, 11, 2, 4096000, 4352, 1114112, 851968, 851968, 532480 };

    cudaEventRecord(evRoot, 0);
    for (int i = 0; i < 3; i++) cudaStreamWaitEvent(st[i], evRoot, 0);

    pool2_kernel<<<(BATCH*14*14 + 255)/256, 256, 0, st[1]>>>(x);
    cudaEventRecord(evPool, st[1]);
    cudaStreamWaitEvent(st[0], evPool, 0);
    pool1_kernel<<<(BATCH*7*7 + 255)/256, 256, 0, st[0]>>>();

    run_branch(b3, d_in, x, st[2]);
    run_branch(b2, d_in, x, st[1]);
    run_branch(b1, d_in, x, st[0]);

    for (int i = 0; i < 3; i++) {
        cudaEventRecord(evDone[i], st[i]);
        cudaStreamWaitEvent(0, evDone[i], 0);
    }
    final_kernel<<<1, 256>>>(out);
}